// round 7
// baseline (speedup 1.0000x reference)
#include <cuda_runtime.h>

#define BATCH 32768
#define TT 21
#define FIN 126
#define GG 32
#define NC 27

#define THREADS 256
#define WPB 8                 // warps per block
#define EPW 4                 // elements per warp
#define XSTRIDE 132           // padded floats per staged row (bank-offset 4)

typedef unsigned long long ull;

// ---------------- packed f32x2 helpers ----------------
__device__ __forceinline__ ull fma2(ull a, ull b, ull c) {
    ull d;
    asm("fma.rn.f32x2 %0, %1, %2, %3;" : "=l"(d) : "l"(a), "l"(b), "l"(c));
    return d;
}
__device__ __forceinline__ ull add2(ull a, ull b) {
    ull d;
    asm("add.rn.f32x2 %0, %1, %2;" : "=l"(d) : "l"(a), "l"(b));
    return d;
}
__device__ __forceinline__ ull bcast2(float v) {
    ull d;
    asm("mov.b64 %0, {%1, %2};" : "=l"(d) : "f"(v), "f"(v));
    return d;
}
__device__ __forceinline__ ull pack2(float lo, float hi) {
    ull d;
    asm("mov.b64 %0, {%1, %2};" : "=l"(d) : "f"(lo), "f"(hi));
    return d;
}
__device__ __forceinline__ void unpack2(float& lo, float& hi, ull v) {
    asm("mov.b64 {%0, %1}, %2;" : "=f"(lo), "=f"(hi) : "l"(v));
}

// Fast activations: MUFU-based, rel err ~1e-6 (threshold 1e-3)
__device__ __forceinline__ float sigm(float x) {
    return __fdividef(1.0f, 1.0f + __expf(-x));
}
__device__ __forceinline__ float tanhg(float x) {
    return __fdividef(2.0f, 1.0f + __expf(-2.0f * x)) - 1.0f;
}

// ---------------- Fused kernel: projection + 2x LSTM + dense + softmax ----------------
// 8 threads per batch element (thread k owns unit k / gates k,8+k,16+k,24+k).
// Per warp: 4 elements. x_t staged per-warp through smem, prefetched 1 step ahead.
__global__ __launch_bounds__(THREADS)
void fused_lstm_kernel(const float* __restrict__ x,
                       const float* __restrict__ W1k, const float* __restrict__ b1,
                       const float* __restrict__ W1r,
                       const float* __restrict__ W2k, const float* __restrict__ W2r,
                       const float* __restrict__ b2,
                       const float* __restrict__ Wd, const float* __restrict__ bd,
                       float* __restrict__ out) {
    __shared__ __align__(16) ulonglong2 sWk[FIN * 8];   // 16128 B: [f*8+k] = (if,go) packs
    __shared__ __align__(16) ulonglong2 sw2a[64];       // W2k [j*8+k]
    __shared__ __align__(16) ulonglong2 sw2b[64];       // W2r [j*8+k]
    __shared__ float xs[WPB * EPW * XSTRIDE];           // 16896 B staged x_t

    int tid = threadIdx.x;

    for (int i = tid; i < FIN * 8; i += THREADS) {
        int f = i >> 3, kk = i & 7;
        const float* w = W1k + f * GG;
        sWk[i] = make_ulonglong2(pack2(w[kk], w[8 + kk]), pack2(w[16 + kk], w[24 + kk]));
    }
    if (tid < 64) {
        int j = tid >> 3, kk = tid & 7;
        const float* p = W2k + j * GG;
        sw2a[tid] = make_ulonglong2(pack2(p[kk], p[8 + kk]), pack2(p[16 + kk], p[24 + kk]));
    } else if (tid < 128) {
        int i = tid - 64;
        int j = i >> 3, kk = i & 7;
        const float* p = W2r + j * GG;
        sw2b[i] = make_ulonglong2(pack2(p[kk], p[8 + kk]), pack2(p[16 + kk], p[24 + kk]));
    }
    __syncthreads();

    int warp = tid >> 5, lane = tid & 31;
    int k = lane & 7;
    int obase = lane & 24;
    int we = lane >> 3;                       // element-within-warp
    int ebase = blockIdx.x * (WPB * EPW) + warp * EPW;
    int e = ebase + we;

    float* xsw = xs + warp * (EPW * XSTRIDE);

    // Staging geometry: idx = lane + 32*i over [0,252): ee = idx/63, cc = idx%63
    int goff[8], soff[8];
    bool act[8];
#pragma unroll
    for (int i = 0; i < 8; ++i) {
        int idx = lane + 32 * i;
        act[i] = (idx < 252);
        int ee = idx / 63;
        int cc = idx - ee * 63;
        if (ee > 3) ee = 3;                   // clamp for inactive lanes (addr unused)
        goff[i] = (ebase + ee) * (TT * FIN) + 2 * cc;
        soff[i] = ee * XSTRIDE + 2 * cc;
    }

    // Per-unit weights/biases in registers
    ull w1if[8], w1go[8];
#pragma unroll
    for (int j = 0; j < 8; ++j) {
        const float* r1 = W1r + j * GG;
        w1if[j] = pack2(r1[k], r1[8 + k]);
        w1go[j] = pack2(r1[16 + k], r1[24 + k]);
    }
    ull b1if = pack2(b1[k], b1[8 + k]);
    ull b1go = pack2(b1[16 + k], b1[24 + k]);
    ull b2if = pack2(b2[k], b2[8 + k]);
    ull b2go = pack2(b2[16 + k], b2[24 + k]);

    float h1 = 0.f, c1 = 0.f, h2 = 0.f, c2 = 0.f;

    // ---- stage t = 0 ----
    float2 st[8];
#pragma unroll
    for (int i = 0; i < 8; ++i)
        if (act[i]) st[i] = *(const float2*)(x + goff[i]);
#pragma unroll
    for (int i = 0; i < 8; ++i)
        if (act[i]) *(float2*)(xsw + soff[i]) = st[i];
    __syncwarp();

    for (int t = 0; t < TT; ++t) {
        // prefetch x_{t+1} into registers (overlaps with compute below)
        if (t < TT - 1) {
#pragma unroll
            for (int i = 0; i < 8; ++i)
                if (act[i]) st[i] = *(const float2*)(x + goff[i] + (t + 1) * FIN);
        }

        // ---- layer 1: input projection + recurrent ----
        ull zifA = b1if, zgoA = b1go, zifB = 0ull, zgoB = 0ull;
        const float* xr = xsw + we * XSTRIDE;
#pragma unroll
        for (int p = 0; p < 63; ++p) {
            float2 xv = *(const float2*)(xr + 2 * p);
            ull xa = bcast2(xv.x), xb = bcast2(xv.y);
            ulonglong2 wA = sWk[(2 * p) * 8 + k];
            ulonglong2 wB = sWk[(2 * p + 1) * 8 + k];
            zifA = fma2(xa, wA.x, zifA);
            zgoA = fma2(xa, wA.y, zgoA);
            zifB = fma2(xb, wB.x, zifB);
            zgoB = fma2(xb, wB.y, zgoB);
        }
#pragma unroll
        for (int j = 0; j < 4; ++j) {
            ull hb = bcast2(__shfl_sync(0xffffffffu, h1, obase | j));
            zifA = fma2(hb, w1if[j], zifA);
            zgoA = fma2(hb, w1go[j], zgoA);
        }
#pragma unroll
        for (int j = 4; j < 8; ++j) {
            ull hb = bcast2(__shfl_sync(0xffffffffu, h1, obase | j));
            zifB = fma2(hb, w1if[j], zifB);
            zgoB = fma2(hb, w1go[j], zgoB);
        }
        {
            ull zif = add2(zifA, zifB), zgo = add2(zgoA, zgoB);
            float zi, zf, zg, zo;
            unpack2(zi, zf, zif);
            unpack2(zg, zo, zgo);
            c1 = sigm(zf) * c1 + sigm(zi) * tanhg(zg);
            h1 = sigm(zo) * tanhg(c1);
        }

        // ---- layer 2 ----
        zifA = b2if; zgoA = b2go; zifB = 0ull; zgoB = 0ull;
#pragma unroll
        for (int j = 0; j < 8; ++j) {
            ull ab = bcast2(__shfl_sync(0xffffffffu, h1, obase | j));
            ull bb = bcast2(__shfl_sync(0xffffffffu, h2, obase | j));
            ulonglong2 wa = sw2a[j * 8 + k];
            ulonglong2 wb = sw2b[j * 8 + k];
            zifA = fma2(ab, wa.x, zifA);
            zgoA = fma2(ab, wa.y, zgoA);
            zifB = fma2(bb, wb.x, zifB);
            zgoB = fma2(bb, wb.y, zgoB);
        }
        {
            ull zif = add2(zifA, zifB), zgo = add2(zgoA, zgoB);
            float zi, zf, zg, zo;
            unpack2(zi, zf, zif);
            unpack2(zg, zo, zgo);
            c2 = sigm(zf) * c2 + sigm(zi) * tanhg(zg);
            h2 = sigm(zo) * tanhg(c2);
        }

        // ---- commit staged x_{t+1} ----
        if (t < TT - 1) {
            __syncwarp();      // WAR: all lanes done reading xs for step t
#pragma unroll
            for (int i = 0; i < 8; ++i)
                if (act[i]) *(float2*)(xsw + soff[i]) = st[i];
            __syncwarp();      // RAW: visible before next step's LDS
        }
    }

    // ---- dense + softmax, distributed over octet ----
    float h2f[8];
#pragma unroll
    for (int j = 0; j < 8; ++j)
        h2f[j] = __shfl_sync(0xffffffffu, h2, obase | j);

    float lg[4];
#pragma unroll
    for (int q = 0; q < 4; ++q) {
        int m = q * 8 + k;
        float acc = (m < NC) ? bd[m] : -1e30f;
        if (m < NC) {
#pragma unroll
            for (int j = 0; j < 8; ++j) acc += h2f[j] * Wd[j * NC + m];
        }
        lg[q] = acc;
    }
    float mx = fmaxf(fmaxf(lg[0], lg[1]), fmaxf(lg[2], lg[3]));
#pragma unroll
    for (int off = 4; off >= 1; off >>= 1)
        mx = fmaxf(mx, __shfl_xor_sync(0xffffffffu, mx, off));
    float s = 0.f;
#pragma unroll
    for (int q = 0; q < 4; ++q) {
        float v = (q * 8 + k < NC) ? __expf(lg[q] - mx) : 0.f;
        lg[q] = v;
        s += v;
    }
#pragma unroll
    for (int off = 4; off >= 1; off >>= 1)
        s += __shfl_xor_sync(0xffffffffu, s, off);
    float inv = __fdividef(1.0f, s);
    float* op = out + (size_t)e * NC;
#pragma unroll
    for (int q = 0; q < 4; ++q) {
        int m = q * 8 + k;
        if (m < NC) op[m] = lg[q] * inv;
    }
}

// ---------------- launch ----------------
extern "C" void kernel_launch(void* const* d_in, const int* in_sizes, int n_in,
                              void* d_out, int out_size) {
    const float* x   = (const float*)d_in[0];
    const float* W1k = (const float*)d_in[1];
    const float* W1r = (const float*)d_in[2];
    const float* b1  = (const float*)d_in[3];
    const float* W2k = (const float*)d_in[4];
    const float* W2r = (const float*)d_in[5];
    const float* b2  = (const float*)d_in[6];
    const float* Wd  = (const float*)d_in[7];
    const float* bd  = (const float*)d_in[8];
    float* out = (float*)d_out;

    fused_lstm_kernel<<<BATCH / (WPB * EPW), THREADS>>>(
        x, W1k, b1, W1r, W2k, W2r, b2, Wd, bd, out);
}

// round 8
// speedup vs baseline: 1.6395x; 1.6395x over previous
#include <cuda_runtime.h>

#define BATCH 32768
#define TT 21
#define FIN 126
#define GG 32
#define NC 27

#define THREADS 128
#define WPB 4                  // warps per block
#define EPW 8                  // elements per warp (2 per octet)
#define XSTR 132               // padded floats per staged row
#define ROWLEN (TT * FIN)      // 2646

typedef unsigned long long ull;

// ---------------- packed f32x2 helpers ----------------
__device__ __forceinline__ ull fma2(ull a, ull b, ull c) {
    ull d;
    asm("fma.rn.f32x2 %0, %1, %2, %3;" : "=l"(d) : "l"(a), "l"(b), "l"(c));
    return d;
}
__device__ __forceinline__ ull bcast2(float v) {
    ull d;
    asm("mov.b64 %0, {%1, %2};" : "=l"(d) : "f"(v), "f"(v));
    return d;
}
__device__ __forceinline__ ull pack2(float lo, float hi) {
    ull d;
    asm("mov.b64 %0, {%1, %2};" : "=l"(d) : "f"(lo), "f"(hi));
    return d;
}
__device__ __forceinline__ void unpack2(float& lo, float& hi, ull v) {
    asm("mov.b64 {%0, %1}, %2;" : "=f"(lo), "=f"(hi) : "l"(v));
}

// Fast activations: MUFU-based, rel err ~1e-6 (threshold 1e-3)
__device__ __forceinline__ float sigm(float x) {
    return __fdividef(1.0f, 1.0f + __expf(-x));
}
__device__ __forceinline__ float tanhg(float x) {
    return __fdividef(2.0f, 1.0f + __expf(-2.0f * x)) - 1.0f;
}

// ---------------- Fused: projection + 2x LSTM + dense + softmax ----------------
// Octet (8 lanes) handles TWO elements; thread k owns unit k of both.
// Weight LDS amortized over the 2 elements; x via per-warp smem slab.
__global__ __launch_bounds__(THREADS)
void fused_lstm_kernel(const float* __restrict__ x,
                       const float* __restrict__ W1k, const float* __restrict__ b1,
                       const float* __restrict__ W1r,
                       const float* __restrict__ W2k, const float* __restrict__ W2r,
                       const float* __restrict__ b2,
                       const float* __restrict__ Wd, const float* __restrict__ bd,
                       float* __restrict__ out) {
    __shared__ __align__(16) ulonglong2 sWk[128 * 8];    // 16 KB, cols 126/127 zero
    __shared__ __align__(16) ulonglong2 sw2a[64];        // W2k [j*8+k]
    __shared__ __align__(16) ulonglong2 sw2b[64];        // W2r [j*8+k]
    __shared__ __align__(16) float xs[WPB * EPW * XSTR]; // 16.9 KB

    int tid = threadIdx.x;

    for (int i = tid; i < 128 * 8; i += THREADS) {
        int f = i >> 3, kk = i & 7;
        if (f < FIN) {
            const float* w = W1k + f * GG;
            sWk[i] = make_ulonglong2(pack2(w[kk], w[8 + kk]),
                                     pack2(w[16 + kk], w[24 + kk]));
        } else {
            sWk[i] = make_ulonglong2(0ull, 0ull);
        }
    }
    if (tid < 64) {
        int j = tid >> 3, kk = tid & 7;
        const float* p = W2k + j * GG;
        sw2a[tid] = make_ulonglong2(pack2(p[kk], p[8 + kk]), pack2(p[16 + kk], p[24 + kk]));
    } else {
        int i = tid - 64;
        int j = i >> 3, kk = i & 7;
        const float* p = W2r + j * GG;
        sw2b[i] = make_ulonglong2(pack2(p[kk], p[8 + kk]), pack2(p[16 + kk], p[24 + kk]));
    }
    for (int i = tid; i < WPB * EPW * XSTR; i += THREADS)
        xs[i] = 0.0f;                       // zero pad cols stay zero forever
    __syncthreads();

    int warp = tid >> 5, lane = tid & 31;
    int k = lane & 7;
    int oct = lane >> 3;
    int obase = lane & 24;
    int ebase = blockIdx.x * (WPB * EPW) + warp * EPW;

    float* xsw = xs + warp * (EPW * XSTR);

    // Staging bases: transfer i (0..15): element ee=i>>1, half=(i&1),
    //   float2 index cc = half*32 + lane (active if cc<63)
    const float* xq = x + (size_t)ebase * ROWLEN + 2 * lane;   // + ee*ROWLEN + half*64 (imm)
    float* sq = xsw + 2 * lane;                                // + ee*XSTR  + half*64 (imm)

    // Per-unit weights/biases in registers
    ull w1if[8], w1go[8];
#pragma unroll
    for (int j = 0; j < 8; ++j) {
        const float* r1 = W1r + j * GG;
        w1if[j] = pack2(r1[k], r1[8 + k]);
        w1go[j] = pack2(r1[16 + k], r1[24 + k]);
    }
    ull b1if = pack2(b1[k], b1[8 + k]);
    ull b1go = pack2(b1[16 + k], b1[24 + k]);
    ull b2if = pack2(b2[k], b2[8 + k]);
    ull b2go = pack2(b2[16 + k], b2[24 + k]);

    float h1[2] = {0.f, 0.f}, c1[2] = {0.f, 0.f};
    float h2[2] = {0.f, 0.f}, c2[2] = {0.f, 0.f};

    float2 st[16];
    bool tail = (lane < 31);    // half==1 transfers active only for lane<31

    // ---- stage t = 0 ----
#pragma unroll
    for (int i = 0; i < 16; ++i) {
        int ee = i >> 1, half = i & 1;
        if (!half || tail)
            st[i] = *(const float2*)(xq + ee * ROWLEN + half * 64);
    }
#pragma unroll
    for (int i = 0; i < 16; ++i) {
        int ee = i >> 1, half = i & 1;
        if (!half || tail)
            *(float2*)(sq + ee * XSTR + half * 64) = st[i];
    }
    __syncwarp();

    const float* xr0 = xsw + (2 * oct) * XSTR;     // element r=0 row
    const float* xr1 = xr0 + XSTR;                 // element r=1 row

    for (int t = 0; t < TT; ++t) {
        // prefetch x_{t+1} into registers (overlaps FFMA block)
        if (t < TT - 1) {
            const float* xqt = xq + (t + 1) * FIN;
#pragma unroll
            for (int i = 0; i < 16; ++i) {
                int ee = i >> 1, half = i & 1;
                if (!half || tail)
                    st[i] = *(const float2*)(xqt + ee * ROWLEN + half * 64);
            }
        }

        // ---- layer 1 projection: 128 padded cols, 2 elements ----
        ull zif0 = b1if, zgo0 = b1go, zif1 = b1if, zgo1 = b1go;
#pragma unroll 8
        for (int p = 0; p < 32; ++p) {
            float4 xa = *(const float4*)(xr0 + 4 * p);
            float4 xb = *(const float4*)(xr1 + 4 * p);
            ulonglong2 w0 = sWk[(4 * p + 0) * 8 + k];
            ulonglong2 w1 = sWk[(4 * p + 1) * 8 + k];
            ulonglong2 w2 = sWk[(4 * p + 2) * 8 + k];
            ulonglong2 w3 = sWk[(4 * p + 3) * 8 + k];
            ull ax = bcast2(xa.x), ay = bcast2(xa.y), az = bcast2(xa.z), aw = bcast2(xa.w);
            ull bx = bcast2(xb.x), by = bcast2(xb.y), bz = bcast2(xb.z), bw = bcast2(xb.w);
            zif0 = fma2(ax, w0.x, zif0); zgo0 = fma2(ax, w0.y, zgo0);
            zif1 = fma2(bx, w0.x, zif1); zgo1 = fma2(bx, w0.y, zgo1);
            zif0 = fma2(ay, w1.x, zif0); zgo0 = fma2(ay, w1.y, zgo0);
            zif1 = fma2(by, w1.x, zif1); zgo1 = fma2(by, w1.y, zgo1);
            zif0 = fma2(az, w2.x, zif0); zgo0 = fma2(az, w2.y, zgo0);
            zif1 = fma2(bz, w2.x, zif1); zgo1 = fma2(bz, w2.y, zgo1);
            zif0 = fma2(aw, w3.x, zif0); zgo0 = fma2(aw, w3.y, zgo0);
            zif1 = fma2(bw, w3.x, zif1); zgo1 = fma2(bw, w3.y, zgo1);
        }

        ull zifr[2] = {zif0, zif1}, zgor[2] = {zgo0, zgo1};

        // ---- layer 1 recurrent + activations (both elements) ----
#pragma unroll
        for (int r = 0; r < 2; ++r) {
            ull zif = zifr[r], zgo = zgor[r];
#pragma unroll
            for (int j = 0; j < 8; ++j) {
                ull hb = bcast2(__shfl_sync(0xffffffffu, h1[r], obase | j));
                zif = fma2(hb, w1if[j], zif);
                zgo = fma2(hb, w1go[j], zgo);
            }
            float zi, zf, zg, zo;
            unpack2(zi, zf, zif);
            unpack2(zg, zo, zgo);
            c1[r] = sigm(zf) * c1[r] + sigm(zi) * tanhg(zg);
            h1[r] = sigm(zo) * tanhg(c1[r]);
        }

        // ---- layer 2 (both elements) ----
#pragma unroll
        for (int r = 0; r < 2; ++r) {
            ull zif = b2if, zgo = b2go;
#pragma unroll
            for (int j = 0; j < 8; ++j) {
                ull ab = bcast2(__shfl_sync(0xffffffffu, h1[r], obase | j));
                ull bb = bcast2(__shfl_sync(0xffffffffu, h2[r], obase | j));
                ulonglong2 wa = sw2a[j * 8 + k];
                ulonglong2 wb = sw2b[j * 8 + k];
                zif = fma2(ab, wa.x, zif);
                zgo = fma2(ab, wa.y, zgo);
                zif = fma2(bb, wb.x, zif);
                zgo = fma2(bb, wb.y, zgo);
            }
            float zi, zf, zg, zo;
            unpack2(zi, zf, zif);
            unpack2(zg, zo, zgo);
            c2[r] = sigm(zf) * c2[r] + sigm(zi) * tanhg(zg);
            h2[r] = sigm(zo) * tanhg(c2[r]);
        }

        // ---- commit staged x_{t+1} ----
        if (t < TT - 1) {
            __syncwarp();                       // WAR on xs
#pragma unroll
            for (int i = 0; i < 16; ++i) {
                int ee = i >> 1, half = i & 1;
                if (!half || tail)
                    *(float2*)(sq + ee * XSTR + half * 64) = st[i];
            }
            __syncwarp();                       // RAW before next LDS
        }
    }

    // ---- dense + softmax per element, distributed over octet ----
#pragma unroll
    for (int r = 0; r < 2; ++r) {
        float h2f[8];
#pragma unroll
        for (int j = 0; j < 8; ++j)
            h2f[j] = __shfl_sync(0xffffffffu, h2[r], obase | j);

        float lg[4];
#pragma unroll
        for (int q = 0; q < 4; ++q) {
            int m = q * 8 + k;
            float acc = (m < NC) ? bd[m] : -1e30f;
            if (m < NC) {
#pragma unroll
                for (int j = 0; j < 8; ++j) acc += h2f[j] * Wd[j * NC + m];
            }
            lg[q] = acc;
        }
        float mx = fmaxf(fmaxf(lg[0], lg[1]), fmaxf(lg[2], lg[3]));
#pragma unroll
        for (int off = 4; off >= 1; off >>= 1)
            mx = fmaxf(mx, __shfl_xor_sync(0xffffffffu, mx, off));
        float s = 0.f;
#pragma unroll
        for (int q = 0; q < 4; ++q) {
            float v = (q * 8 + k < NC) ? __expf(lg[q] - mx) : 0.f;
            lg[q] = v;
            s += v;
        }
#pragma unroll
        for (int off = 4; off >= 1; off >>= 1)
            s += __shfl_xor_sync(0xffffffffu, s, off);
        float inv = __fdividef(1.0f, s);
        int e = ebase + 2 * oct + r;
        float* op = out + (size_t)e * NC;
#pragma unroll
        for (int q = 0; q < 4; ++q) {
            int m = q * 8 + k;
            if (m < NC) op[m] = lg[q] * inv;
        }
    }
}

// ---------------- launch ----------------
extern "C" void kernel_launch(void* const* d_in, const int* in_sizes, int n_in,
                              void* d_out, int out_size) {
    const float* x   = (const float*)d_in[0];
    const float* W1k = (const float*)d_in[1];
    const float* W1r = (const float*)d_in[2];
    const float* b1  = (const float*)d_in[3];
    const float* W2k = (const float*)d_in[4];
    const float* W2r = (const float*)d_in[5];
    const float* b2  = (const float*)d_in[6];
    const float* Wd  = (const float*)d_in[7];
    const float* bd  = (const float*)d_in[8];
    float* out = (float*)d_out;

    fused_lstm_kernel<<<BATCH / (WPB * EPW), THREADS>>>(
        x, W1k, b1, W1r, W2k, W2r, b2, Wd, bd, out);
}

// round 10
// speedup vs baseline: 1.8776x; 1.1452x over previous
#include <cuda_runtime.h>
#include <cstdint>

#define BATCH 32768
#define TT 21
#define FIN 126
#define GG 32
#define NC 27

#define THREADS 64
#define WPB 2                  // warps per block
#define EPW 16                 // elements per warp (4 per octet-thread)
#define XSTR 132               // padded floats per staged row
#define ROWLEN (TT * FIN)      // 2646

typedef unsigned long long ull;

// ---------------- packed f32x2 helpers ----------------
__device__ __forceinline__ ull fma2(ull a, ull b, ull c) {
    ull d;
    asm("fma.rn.f32x2 %0, %1, %2, %3;" : "=l"(d) : "l"(a), "l"(b), "l"(c));
    return d;
}
__device__ __forceinline__ ull bcast2(float v) {
    ull d;
    asm("mov.b64 %0, {%1, %2};" : "=l"(d) : "f"(v), "f"(v));
    return d;
}
__device__ __forceinline__ ull pack2(float lo, float hi) {
    ull d;
    asm("mov.b64 %0, {%1, %2};" : "=l"(d) : "f"(lo), "f"(hi));
    return d;
}
__device__ __forceinline__ void unpack2(float& lo, float& hi, ull v) {
    asm("mov.b64 {%0, %1}, %2;" : "=f"(lo), "=f"(hi) : "l"(v));
}
__device__ __forceinline__ uint32_t smem_u32(const void* p) {
    uint32_t a;
    asm("{ .reg .u64 t; cvta.to.shared.u64 t, %1; cvt.u32.u64 %0, t; }" : "=r"(a) : "l"(p));
    return a;
}
__device__ __forceinline__ void cpa8(uint32_t saddr, const void* g) {
    asm volatile("cp.async.ca.shared.global [%0], [%1], 8;" :: "r"(saddr), "l"(g) : "memory");
}
#define CPA_COMMIT() asm volatile("cp.async.commit_group;" ::: "memory")
#define CPA_WAIT0()  asm volatile("cp.async.wait_group 0;" ::: "memory")

// Fast activations: MUFU-based, rel err ~1e-6 (threshold 1e-3)
__device__ __forceinline__ float sigm(float x) {
    return __fdividef(1.0f, 1.0f + __expf(-x));
}
__device__ __forceinline__ float tanhg(float x) {
    return __fdividef(2.0f, 1.0f + __expf(-2.0f * x)) - 1.0f;
}

// ---------------- Fused: projection + 2x LSTM + dense + softmax ----------------
// Octet (8 lanes) handles FOUR elements; thread k owns unit k of all four.
// Weight LDS amortized over 4 elements; x staged per-warp via cp.async.
__global__ __launch_bounds__(THREADS)
void fused_lstm_kernel(const float* __restrict__ x,
                       const float* __restrict__ W1k, const float* __restrict__ b1,
                       const float* __restrict__ W1r,
                       const float* __restrict__ W2k, const float* __restrict__ W2r,
                       const float* __restrict__ b2,
                       const float* __restrict__ Wd, const float* __restrict__ bd,
                       float* __restrict__ out) {
    __shared__ __align__(16) ulonglong2 sWk[128 * 8];     // 16 KB, cols 126/127 zero
    __shared__ __align__(16) ulonglong2 sw2a[64];         // W2k [j*8+k]
    __shared__ __align__(16) ulonglong2 sw2b[64];         // W2r [j*8+k]
    __shared__ __align__(16) float xs[WPB * EPW * XSTR];  // 16.9 KB

    int tid = threadIdx.x;

    for (int i = tid; i < 128 * 8; i += THREADS) {
        int f = i >> 3, kk = i & 7;
        if (f < FIN) {
            const float* w = W1k + f * GG;
            sWk[i] = make_ulonglong2(pack2(w[kk], w[8 + kk]),
                                     pack2(w[16 + kk], w[24 + kk]));
        } else {
            sWk[i] = make_ulonglong2(0ull, 0ull);
        }
    }
    for (int i = tid; i < 64; i += THREADS) {
        int j = i >> 3, kk = i & 7;
        const float* pa = W2k + j * GG;
        const float* pb = W2r + j * GG;
        sw2a[i] = make_ulonglong2(pack2(pa[kk], pa[8 + kk]), pack2(pa[16 + kk], pa[24 + kk]));
        sw2b[i] = make_ulonglong2(pack2(pb[kk], pb[8 + kk]), pack2(pb[16 + kk], pb[24 + kk]));
    }
    __syncthreads();

    int warp = tid >> 5, lane = tid & 31;
    int k = lane & 7;
    int oct = lane >> 3;
    int obase = lane & 24;
    int ebase = blockIdx.x * (WPB * EPW) + warp * EPW;

    float* xsw = xs + warp * (EPW * XSTR);
    const uint32_t slab = smem_u32(xsw);

    // staging: 32 transfers i: row = i>>1 (0..15), col2 = (i&1)*32 + lane (8B chunks)
    // guard: very last 8B chunk of x (element BATCH-1, t=TT-1, chunk 63) is OOB
    bool lastw = (blockIdx.x == gridDim.x - 1) && (warp == WPB - 1);
    const char* xgbase = (const char*)(x + (size_t)ebase * ROWLEN) + 8 * lane;
    const uint32_t sbase_lane = slab + 8 * lane;

    // Per-unit weights/biases in registers
    ull w1if[8], w1go[8];
#pragma unroll
    for (int j = 0; j < 8; ++j) {
        const float* r1 = W1r + j * GG;
        w1if[j] = pack2(r1[k], r1[8 + k]);
        w1go[j] = pack2(r1[16 + k], r1[24 + k]);
    }
    ull b1if = pack2(b1[k], b1[8 + k]);
    ull b1go = pack2(b1[16 + k], b1[24 + k]);
    ull b2if = pack2(b2[k], b2[8 + k]);
    ull b2go = pack2(b2[16 + k], b2[24 + k]);

    float h1[4] = {0.f, 0.f, 0.f, 0.f}, c1[4] = {0.f, 0.f, 0.f, 0.f};
    float h2[4] = {0.f, 0.f, 0.f, 0.f}, c2[4] = {0.f, 0.f, 0.f, 0.f};

    // ---- stage t = 0 ----
    {
#pragma unroll
        for (int i = 0; i < 32; ++i) {
            int row = i >> 1;
            size_t goff = (size_t)row * (ROWLEN * 4) + (size_t)(i & 1) * 256;
            uint32_t soff = row * (XSTR * 4) + (i & 1) * 256;
            cpa8(sbase_lane + soff, xgbase + goff);
        }
        CPA_COMMIT();
        CPA_WAIT0();
        __syncwarp();
    }

    // element of (oct, r) = ebase + 4r + oct; slab row = 4r + oct
    const float* xr0 = xsw + (0 + oct) * XSTR;
    const float* xr1 = xsw + (4 + oct) * XSTR;
    const float* xr2 = xsw + (8 + oct) * XSTR;
    const float* xr3 = xsw + (12 + oct) * XSTR;

    for (int t = 0; t < TT; ++t) {
        // ---- layer 1 projection: 128 padded cols, 4 elements ----
        ull zif[4], zgo[4];
#pragma unroll
        for (int r = 0; r < 4; ++r) { zif[r] = b1if; zgo[r] = b1go; }

#pragma unroll 4
        for (int p = 0; p < 32; ++p) {
            float4 v0 = *(const float4*)(xr0 + 4 * p);
            float4 v1 = *(const float4*)(xr1 + 4 * p);
            float4 v2 = *(const float4*)(xr2 + 4 * p);
            float4 v3 = *(const float4*)(xr3 + 4 * p);
            ulonglong2 w0 = sWk[(4 * p + 0) * 8 + k];
            ulonglong2 w1 = sWk[(4 * p + 1) * 8 + k];
            ulonglong2 w2 = sWk[(4 * p + 2) * 8 + k];
            ulonglong2 w3 = sWk[(4 * p + 3) * 8 + k];
            ull b;
            b = bcast2(v0.x); zif[0] = fma2(b, w0.x, zif[0]); zgo[0] = fma2(b, w0.y, zgo[0]);
            b = bcast2(v1.x); zif[1] = fma2(b, w0.x, zif[1]); zgo[1] = fma2(b, w0.y, zgo[1]);
            b = bcast2(v2.x); zif[2] = fma2(b, w0.x, zif[2]); zgo[2] = fma2(b, w0.y, zgo[2]);
            b = bcast2(v3.x); zif[3] = fma2(b, w0.x, zif[3]); zgo[3] = fma2(b, w0.y, zgo[3]);
            b = bcast2(v0.y); zif[0] = fma2(b, w1.x, zif[0]); zgo[0] = fma2(b, w1.y, zgo[0]);
            b = bcast2(v1.y); zif[1] = fma2(b, w1.x, zif[1]); zgo[1] = fma2(b, w1.y, zgo[1]);
            b = bcast2(v2.y); zif[2] = fma2(b, w1.x, zif[2]); zgo[2] = fma2(b, w1.y, zgo[2]);
            b = bcast2(v3.y); zif[3] = fma2(b, w1.x, zif[3]); zgo[3] = fma2(b, w1.y, zgo[3]);
            b = bcast2(v0.z); zif[0] = fma2(b, w2.x, zif[0]); zgo[0] = fma2(b, w2.y, zgo[0]);
            b = bcast2(v1.z); zif[1] = fma2(b, w2.x, zif[1]); zgo[1] = fma2(b, w2.y, zgo[1]);
            b = bcast2(v2.z); zif[2] = fma2(b, w2.x, zif[2]); zgo[2] = fma2(b, w2.y, zgo[2]);
            b = bcast2(v3.z); zif[3] = fma2(b, w2.x, zif[3]); zgo[3] = fma2(b, w2.y, zgo[3]);
            b = bcast2(v0.w); zif[0] = fma2(b, w3.x, zif[0]); zgo[0] = fma2(b, w3.y, zgo[0]);
            b = bcast2(v1.w); zif[1] = fma2(b, w3.x, zif[1]); zgo[1] = fma2(b, w3.y, zgo[1]);
            b = bcast2(v2.w); zif[2] = fma2(b, w3.x, zif[2]); zgo[2] = fma2(b, w3.y, zgo[2]);
            b = bcast2(v3.w); zif[3] = fma2(b, w3.x, zif[3]); zgo[3] = fma2(b, w3.y, zgo[3]);
        }

        // ---- stage x_{t+1} (async; slab reads for t are done; warp-lockstep => WAR safe) ----
        if (t < TT - 1) {
            const char* xgt = xgbase + (size_t)(t + 1) * (FIN * 4);
#pragma unroll
            for (int i = 0; i < 32; ++i) {
                int row = i >> 1;
                size_t goff = (size_t)row * (ROWLEN * 4) + (size_t)(i & 1) * 256;
                uint32_t soff = row * (XSTR * 4) + (i & 1) * 256;
                if (i == 31 && lane == 31 && t + 1 == TT - 1 && lastw)
                    continue;   // last 8B of x would be OOB; cols 126/127 have zero weights
                cpa8(sbase_lane + soff, xgt + goff);
            }
            CPA_COMMIT();
        }

        // ---- layer 1 recurrent + activations ----
#pragma unroll
        for (int r = 0; r < 4; ++r) {
            ull zi2 = zif[r], zg2 = zgo[r];
#pragma unroll
            for (int j = 0; j < 8; ++j) {
                ull hb = bcast2(__shfl_sync(0xffffffffu, h1[r], obase | j));
                zi2 = fma2(hb, w1if[j], zi2);
                zg2 = fma2(hb, w1go[j], zg2);
            }
            float zi, zf, zg, zo;
            unpack2(zi, zf, zi2);
            unpack2(zg, zo, zg2);
            c1[r] = sigm(zf) * c1[r] + sigm(zi) * tanhg(zg);
            h1[r] = sigm(zo) * tanhg(c1[r]);
        }

        // ---- layer 2 ----
#pragma unroll
        for (int r = 0; r < 4; ++r) {
            ull zi2 = b2if, zg2 = b2go;
#pragma unroll
            for (int j = 0; j < 8; ++j) {
                ull ab = bcast2(__shfl_sync(0xffffffffu, h1[r], obase | j));
                ull bb = bcast2(__shfl_sync(0xffffffffu, h2[r], obase | j));
                ulonglong2 wa = sw2a[j * 8 + k];
                ulonglong2 wb = sw2b[j * 8 + k];
                zi2 = fma2(ab, wa.x, zi2);
                zg2 = fma2(ab, wa.y, zg2);
                zi2 = fma2(bb, wb.x, zi2);
                zg2 = fma2(bb, wb.y, zg2);
            }
            float zi, zf, zg, zo;
            unpack2(zi, zf, zi2);
            unpack2(zg, zo, zg2);
            c2[r] = sigm(zf) * c2[r] + sigm(zi) * tanhg(zg);
            h2[r] = sigm(zo) * tanhg(c2[r]);
        }

        // ---- ensure staged x_{t+1} landed ----
        if (t < TT - 1) {
            CPA_WAIT0();
            __syncwarp();
        }
    }

    // ---- dense + softmax per element, distributed over octet ----
#pragma unroll
    for (int r = 0; r < 4; ++r) {
        float h2f[8];
#pragma unroll
        for (int j = 0; j < 8; ++j)
            h2f[j] = __shfl_sync(0xffffffffu, h2[r], obase | j);

        float lg[4];
#pragma unroll
        for (int q = 0; q < 4; ++q) {
            int m = q * 8 + k;
            float acc = (m < NC) ? bd[m] : -1e30f;
            if (m < NC) {
#pragma unroll
                for (int j = 0; j < 8; ++j) acc += h2f[j] * Wd[j * NC + m];
            }
            lg[q] = acc;
        }
        float mx = fmaxf(fmaxf(lg[0], lg[1]), fmaxf(lg[2], lg[3]));
#pragma unroll
        for (int off = 4; off >= 1; off >>= 1)
            mx = fmaxf(mx, __shfl_xor_sync(0xffffffffu, mx, off));
        float s = 0.f;
#pragma unroll
        for (int q = 0; q < 4; ++q) {
            float v = (q * 8 + k < NC) ? __expf(lg[q] - mx) : 0.f;
            lg[q] = v;
            s += v;
        }
#pragma unroll
        for (int off = 4; off >= 1; off >>= 1)
            s += __shfl_xor_sync(0xffffffffu, s, off);
        float inv = __fdividef(1.0f, s);
        int e = ebase + 4 * r + oct;
        float* op = out + (size_t)e * NC;
#pragma unroll
        for (int q = 0; q < 4; ++q) {
            int m = q * 8 + k;
            if (m < NC) op[m] = lg[q] * inv;
        }
    }
}

// ---------------- launch ----------------
extern "C" void kernel_launch(void* const* d_in, const int* in_sizes, int n_in,
                              void* d_out, int out_size) {
    const float* x   = (const float*)d_in[0];
    const float* W1k = (const float*)d_in[1];
    const float* W1r = (const float*)d_in[2];
    const float* b1  = (const float*)d_in[3];
    const float* W2k = (const float*)d_in[4];
    const float* W2r = (const float*)d_in[5];
    const float* b2  = (const float*)d_in[6];
    const float* Wd  = (const float*)d_in[7];
    const float* bd  = (const float*)d_in[8];
    float* out = (float*)d_out;

    fused_lstm_kernel<<<BATCH / (WPB * EPW), THREADS>>>(
        x, W1k, b1, W1r, W2k, W2r, b2, Wd, bd, out);
}

// round 14
// speedup vs baseline: 2.0800x; 1.1078x over previous
#include <cuda_runtime.h>
#include <cstdint>

#define BATCH 32768
#define TT 21
#define FIN 126
#define GG 32
#define NC 27

#define THREADS 128
#define WPB 4                  // warps per block
#define EPW 16                 // elements per warp (4 per octet-thread)
#define XSTR 132               // padded floats per staged row
#define ROWLEN (TT * FIN)      // 2646

// dynamic smem arena layout (bytes)
#define SM_XS    0
#define XS_BYTES (WPB * EPW * XSTR * 4)          // 33792
#define SM_WK    XS_BYTES                        // 33792, 128*8 ulonglong2 = 16384
#define SM_W2A   (SM_WK + 16384)                 // 50176, 64 ulonglong2 = 1024
#define SM_W2B   (SM_W2A + 1024)                 // 51200, 1024
#define SMEM_TOTAL (SM_W2B + 1024)               // 52224

typedef unsigned long long ull;

// ---------------- packed f32x2 helpers ----------------
__device__ __forceinline__ ull fma2(ull a, ull b, ull c) {
    ull d;
    asm("fma.rn.f32x2 %0, %1, %2, %3;" : "=l"(d) : "l"(a), "l"(b), "l"(c));
    return d;
}
__device__ __forceinline__ ull bcast2(float v) {
    ull d;
    asm("mov.b64 %0, {%1, %2};" : "=l"(d) : "f"(v), "f"(v));
    return d;
}
__device__ __forceinline__ ull pack2(float lo, float hi) {
    ull d;
    asm("mov.b64 %0, {%1, %2};" : "=l"(d) : "f"(lo), "f"(hi));
    return d;
}
__device__ __forceinline__ void unpack2(float& lo, float& hi, ull v) {
    asm("mov.b64 {%0, %1}, %2;" : "=f"(lo), "=f"(hi) : "l"(v));
}
__device__ __forceinline__ uint32_t smem_u32(const void* p) {
    uint32_t a;
    asm("{ .reg .u64 t; cvta.to.shared.u64 t, %1; cvt.u32.u64 %0, t; }" : "=r"(a) : "l"(p));
    return a;
}
__device__ __forceinline__ void cpa8(uint32_t saddr, const void* g) {
    asm volatile("cp.async.ca.shared.global [%0], [%1], 8;" :: "r"(saddr), "l"(g) : "memory");
}
#define CPA_COMMIT() asm volatile("cp.async.commit_group;" ::: "memory")
#define CPA_WAIT0()  asm volatile("cp.async.wait_group 0;" ::: "memory")

// Fast activations: MUFU-based, rel err ~1e-6 (threshold 1e-3)
__device__ __forceinline__ float sigm(float x) {
    return __fdividef(1.0f, 1.0f + __expf(-x));
}
__device__ __forceinline__ float tanhg(float x) {
    return __fdividef(2.0f, 1.0f + __expf(-2.0f * x)) - 1.0f;
}

// ---------------- Fused: projection + 2x LSTM + dense + softmax ----------------
// Octet (8 lanes) handles FOUR elements; thread k owns unit k of all four.
// 4 warps per CTA share one weight image (halves smem/warp -> 2x occupancy).
__global__ __launch_bounds__(THREADS)
void fused_lstm_kernel(const float* __restrict__ x,
                       const float* __restrict__ W1k, const float* __restrict__ b1,
                       const float* __restrict__ W1r,
                       const float* __restrict__ W2k, const float* __restrict__ W2r,
                       const float* __restrict__ b2,
                       const float* __restrict__ Wd, const float* __restrict__ bd,
                       float* __restrict__ out) {
    extern __shared__ __align__(16) char sm[];
    float* xs = (float*)(sm + SM_XS);                       // WPB*EPW*XSTR floats
    ulonglong2* sWk = (ulonglong2*)(sm + SM_WK);            // 128*8, cols 126/127 zero
    ulonglong2* sw2a = (ulonglong2*)(sm + SM_W2A);          // W2k [j*8+k]
    ulonglong2* sw2b = (ulonglong2*)(sm + SM_W2B);          // W2r [j*8+k]

    int tid = threadIdx.x;

    for (int i = tid; i < 128 * 8; i += THREADS) {
        int f = i >> 3, kk = i & 7;
        if (f < FIN) {
            const float* w = W1k + f * GG;
            sWk[i] = make_ulonglong2(pack2(w[kk], w[8 + kk]),
                                     pack2(w[16 + kk], w[24 + kk]));
        } else {
            sWk[i] = make_ulonglong2(0ull, 0ull);
        }
    }
    for (int i = tid; i < 64; i += THREADS) {
        int j = i >> 3, kk = i & 7;
        const float* pa = W2k + j * GG;
        const float* pb = W2r + j * GG;
        sw2a[i] = make_ulonglong2(pack2(pa[kk], pa[8 + kk]), pack2(pa[16 + kk], pa[24 + kk]));
        sw2b[i] = make_ulonglong2(pack2(pb[kk], pb[8 + kk]), pack2(pb[16 + kk], pb[24 + kk]));
    }
    __syncthreads();

    int warp = tid >> 5, lane = tid & 31;
    int k = lane & 7;
    int oct = lane >> 3;
    int obase = lane & 24;
    int ebase = blockIdx.x * (WPB * EPW) + warp * EPW;

    float* xsw = xs + warp * (EPW * XSTR);
    const uint32_t slab = smem_u32(xsw);

    // staging: 32 transfers i: row = i>>1 (0..15), 8B chunk index = (i&1)*32 + lane
    // guard: very last 8B chunk of x (element BATCH-1, t=TT-1) is OOB
    bool lastw = (blockIdx.x == gridDim.x - 1) && (warp == WPB - 1);
    const char* xgbase = (const char*)(x + (size_t)ebase * ROWLEN) + 8 * lane;
    const uint32_t sbase_lane = slab + 8 * lane;

    // Per-unit weights/biases in registers
    ull w1if[8], w1go[8];
#pragma unroll
    for (int j = 0; j < 8; ++j) {
        const float* r1 = W1r + j * GG;
        w1if[j] = pack2(r1[k], r1[8 + k]);
        w1go[j] = pack2(r1[16 + k], r1[24 + k]);
    }
    ull b1if = pack2(b1[k], b1[8 + k]);
    ull b1go = pack2(b1[16 + k], b1[24 + k]);
    ull b2if = pack2(b2[k], b2[8 + k]);
    ull b2go = pack2(b2[16 + k], b2[24 + k]);

    float h1[4] = {0.f, 0.f, 0.f, 0.f}, c1[4] = {0.f, 0.f, 0.f, 0.f};
    float h2[4] = {0.f, 0.f, 0.f, 0.f}, c2[4] = {0.f, 0.f, 0.f, 0.f};

    // ---- stage t = 0 ----
    {
#pragma unroll
        for (int i = 0; i < 32; ++i) {
            int row = i >> 1;
            size_t goff = (size_t)row * (ROWLEN * 4) + (size_t)(i & 1) * 256;
            uint32_t soff = row * (XSTR * 4) + (i & 1) * 256;
            cpa8(sbase_lane + soff, xgbase + goff);
        }
        CPA_COMMIT();
        CPA_WAIT0();
        __syncwarp();
    }

    // element of (oct, r) = ebase + 4r + oct; slab row = 4r + oct
    const float* xr0 = xsw + (0 + oct) * XSTR;
    const float* xr1 = xsw + (4 + oct) * XSTR;
    const float* xr2 = xsw + (8 + oct) * XSTR;
    const float* xr3 = xsw + (12 + oct) * XSTR;

    for (int t = 0; t < TT; ++t) {
        // ---- layer 1 projection: 128 padded cols, 4 elements ----
        ull zif[4], zgo[4];
#pragma unroll
        for (int r = 0; r < 4; ++r) { zif[r] = b1if; zgo[r] = b1go; }

#pragma unroll 4
        for (int p = 0; p < 32; ++p) {
            float4 v0 = *(const float4*)(xr0 + 4 * p);
            float4 v1 = *(const float4*)(xr1 + 4 * p);
            float4 v2 = *(const float4*)(xr2 + 4 * p);
            float4 v3 = *(const float4*)(xr3 + 4 * p);
            ulonglong2 w0 = sWk[(4 * p + 0) * 8 + k];
            ulonglong2 w1 = sWk[(4 * p + 1) * 8 + k];
            ulonglong2 w2 = sWk[(4 * p + 2) * 8 + k];
            ulonglong2 w3 = sWk[(4 * p + 3) * 8 + k];
            ull b;
            b = bcast2(v0.x); zif[0] = fma2(b, w0.x, zif[0]); zgo[0] = fma2(b, w0.y, zgo[0]);
            b = bcast2(v1.x); zif[1] = fma2(b, w0.x, zif[1]); zgo[1] = fma2(b, w0.y, zgo[1]);
            b = bcast2(v2.x); zif[2] = fma2(b, w0.x, zif[2]); zgo[2] = fma2(b, w0.y, zgo[2]);
            b = bcast2(v3.x); zif[3] = fma2(b, w0.x, zif[3]); zgo[3] = fma2(b, w0.y, zgo[3]);
            b = bcast2(v0.y); zif[0] = fma2(b, w1.x, zif[0]); zgo[0] = fma2(b, w1.y, zgo[0]);
            b = bcast2(v1.y); zif[1] = fma2(b, w1.x, zif[1]); zgo[1] = fma2(b, w1.y, zgo[1]);
            b = bcast2(v2.y); zif[2] = fma2(b, w1.x, zif[2]); zgo[2] = fma2(b, w1.y, zgo[2]);
            b = bcast2(v3.y); zif[3] = fma2(b, w1.x, zif[3]); zgo[3] = fma2(b, w1.y, zgo[3]);
            b = bcast2(v0.z); zif[0] = fma2(b, w2.x, zif[0]); zgo[0] = fma2(b, w2.y, zgo[0]);
            b = bcast2(v1.z); zif[1] = fma2(b, w2.x, zif[1]); zgo[1] = fma2(b, w2.y, zgo[1]);
            b = bcast2(v2.z); zif[2] = fma2(b, w2.x, zif[2]); zgo[2] = fma2(b, w2.y, zgo[2]);
            b = bcast2(v3.z); zif[3] = fma2(b, w2.x, zif[3]); zgo[3] = fma2(b, w2.y, zgo[3]);
            b = bcast2(v0.w); zif[0] = fma2(b, w3.x, zif[0]); zgo[0] = fma2(b, w3.y, zgo[0]);
            b = bcast2(v1.w); zif[1] = fma2(b, w3.x, zif[1]); zgo[1] = fma2(b, w3.y, zgo[1]);
            b = bcast2(v2.w); zif[2] = fma2(b, w3.x, zif[2]); zgo[2] = fma2(b, w3.y, zgo[2]);
            b = bcast2(v3.w); zif[3] = fma2(b, w3.x, zif[3]); zgo[3] = fma2(b, w3.y, zgo[3]);
        }

        // ---- stage x_{t+1} (async; slab reads for t done; warp-lockstep => WAR safe) ----
        if (t < TT - 1) {
            const char* xgt = xgbase + (size_t)(t + 1) * (FIN * 4);
#pragma unroll
            for (int i = 0; i < 32; ++i) {
                int row = i >> 1;
                size_t goff = (size_t)row * (ROWLEN * 4) + (size_t)(i & 1) * 256;
                uint32_t soff = row * (XSTR * 4) + (i & 1) * 256;
                if (i == 31 && lane == 31 && t + 1 == TT - 1 && lastw)
                    continue;   // last 8B of x would be OOB; cols 126/127 have zero weights
                cpa8(sbase_lane + soff, xgt + goff);
            }
            CPA_COMMIT();
        }

        // ---- layer 1 recurrent + activations ----
#pragma unroll
        for (int r = 0; r < 4; ++r) {
            ull zi2 = zif[r], zg2 = zgo[r];
#pragma unroll
            for (int j = 0; j < 8; ++j) {
                ull hb = bcast2(__shfl_sync(0xffffffffu, h1[r], obase | j));
                zi2 = fma2(hb, w1if[j], zi2);
                zg2 = fma2(hb, w1go[j], zg2);
            }
            float zi, zf, zg, zo;
            unpack2(zi, zf, zi2);
            unpack2(zg, zo, zg2);
            c1[r] = sigm(zf) * c1[r] + sigm(zi) * tanhg(zg);
            h1[r] = sigm(zo) * tanhg(c1[r]);
        }

        // ---- layer 2 ----
#pragma unroll
        for (int r = 0; r < 4; ++r) {
            ull zi2 = b2if, zg2 = b2go;
#pragma unroll
            for (int j = 0; j < 8; ++j) {
                ull ab = bcast2(__shfl_sync(0xffffffffu, h1[r], obase | j));
                ull bb = bcast2(__shfl_sync(0xffffffffu, h2[r], obase | j));
                ulonglong2 wa = sw2a[j * 8 + k];
                ulonglong2 wb = sw2b[j * 8 + k];
                zi2 = fma2(ab, wa.x, zi2);
                zg2 = fma2(ab, wa.y, zg2);
                zi2 = fma2(bb, wb.x, zi2);
                zg2 = fma2(bb, wb.y, zg2);
            }
            float zi, zf, zg, zo;
            unpack2(zi, zf, zi2);
            unpack2(zg, zo, zg2);
            c2[r] = sigm(zf) * c2[r] + sigm(zi) * tanhg(zg);
            h2[r] = sigm(zo) * tanhg(c2[r]);
        }

        // ---- ensure staged x_{t+1} landed ----
        if (t < TT - 1) {
            CPA_WAIT0();
            __syncwarp();
        }
    }

    // ---- dense + softmax per element, distributed over octet ----
#pragma unroll
    for (int r = 0; r < 4; ++r) {
        float h2f[8];
#pragma unroll
        for (int j = 0; j < 8; ++j)
            h2f[j] = __shfl_sync(0xffffffffu, h2[r], obase | j);

        float lg[4];
#pragma unroll
        for (int q = 0; q < 4; ++q) {
            int m = q * 8 + k;
            float acc = (m < NC) ? bd[m] : -1e30f;
            if (m < NC) {
#pragma unroll
                for (int j = 0; j < 8; ++j) acc += h2f[j] * Wd[j * NC + m];
            }
            lg[q] = acc;
        }
        float mx = fmaxf(fmaxf(lg[0], lg[1]), fmaxf(lg[2], lg[3]));
#pragma unroll
        for (int off = 4; off >= 1; off >>= 1)
            mx = fmaxf(mx, __shfl_xor_sync(0xffffffffu, mx, off));
        float s = 0.f;
#pragma unroll
        for (int q = 0; q < 4; ++q) {
            float v = (q * 8 + k < NC) ? __expf(lg[q] - mx) : 0.f;
            lg[q] = v;
            s += v;
        }
#pragma unroll
        for (int off = 4; off >= 1; off >>= 1)
            s += __shfl_xor_sync(0xffffffffu, s, off);
        float inv = __fdividef(1.0f, s);
        int e = ebase + 4 * r + oct;
        float* op = out + (size_t)e * NC;
#pragma unroll
        for (int q = 0; q < 4; ++q) {
            int m = q * 8 + k;
            if (m < NC) op[m] = lg[q] * inv;
        }
    }
}

// ---------------- launch ----------------
extern "C" void kernel_launch(void* const* d_in, const int* in_sizes, int n_in,
                              void* d_out, int out_size) {
    const float* x   = (const float*)d_in[0];
    const float* W1k = (const float*)d_in[1];
    const float* W1r = (const float*)d_in[2];
    const float* b1  = (const float*)d_in[3];
    const float* W2k = (const float*)d_in[4];
    const float* W2r = (const float*)d_in[5];
    const float* b2  = (const float*)d_in[6];
    const float* Wd  = (const float*)d_in[7];
    const float* bd  = (const float*)d_in[8];
    float* out = (float*)d_out;

    // 52224 B dynamic smem > 48KB default: opt-in required (proven capture-safe in R4/R5)
    cudaFuncSetAttribute(fused_lstm_kernel,
                         cudaFuncAttributeMaxDynamicSharedMemorySize, SMEM_TOTAL);
    fused_lstm_kernel<<<BATCH / (WPB * EPW), THREADS, SMEM_TOTAL>>>(
        x, W1k, b1, W1r, W2k, W2r, b2, Wd, bd, out);
}